// round 6
// baseline (speedup 1.0000x reference)
#include <cuda_runtime.h>
#include <math.h>
#include <stdint.h>

// Problem dims (fixed by the dataset)
#define BB 32
#define DD 1024
#define HH 1024

#define GEMM_BLOCKS 32        // h-tiles of 32: 1024/32
#define STREAM_BLOCKS 1024
#define NTHREADS 256
#define N4 ((BB*DD*HH)/4)     // 8388608 float4

// stream: per-block contiguous chunk of 8192 float4 (128KB) = 16 stages x 512 f4
#define STAGE_F4 512
#define NSTAGES 16
#define CHUNK_F4 (STAGE_F4 * NSTAGES)   // 8192; 2^23/8192 = 1024 blocks exact
#define DEPTH 6                          // ring stages resident in smem

// d_out layout (float32, reference return order):
//   out   [B,H]      @ 0
//   u_new [B,H]      @ 32768
//   E_w   [B,D,H]    @ 65536
//   E_b   [B,H]      @ 65536 + 33554432
#define OFF_UNEW (BB*HH)
#define OFF_EW   (2*BB*HH)
#define OFF_EB   (2*BB*HH + BB*DD*HH)

__device__ __forceinline__ uint32_t smem_u32(const void* p) {
    return (uint32_t)__cvta_generic_to_shared(p);
}
__device__ __forceinline__ void cp16(uint32_t dst, const void* src) {
    asm volatile("cp.async.cg.shared.global [%0], [%1], 16;"
                 :: "r"(dst), "l"(src) : "memory");
}

__global__ void diag_rtrl_fused_kernel(
    const float* __restrict__ x,   // [B,D]
    const float* __restrict__ w,   // [D,H]
    const float* __restrict__ b,   // [H]
    const float* __restrict__ u,   // [B,H]
    const float* __restrict__ Ew,  // [1,B,D,H]
    const float* __restrict__ Eb,  // [1,B,H]
    float* __restrict__ out)       // packed outputs
{
    // 48KB ring (stream path); GEMM path aliases its tiles inside it
    __shared__ __align__(16) float4 ring[DEPTH * STAGE_F4];  // 49152 bytes

    if (blockIdx.x >= GEMM_BLOCKS) {
        // ---------------- E_w streaming path (barrier-free cp.async ring) ---
        // E_new_w[i,d,h] = 0.9*E_w[i,d,h] + x[i,d]; f4 index g -> x[g>>8]
        const int t    = threadIdx.x;
        const int base = (blockIdx.x - GEMM_BLOCKS) * CHUNK_F4;
        const float4* __restrict__ gin =
            reinterpret_cast<const float4*>(Ew) + base;
        float4* __restrict__ gout =
            reinterpret_cast<float4*>(&out[OFF_EW]) + base;
        const uint32_t sa = smem_u32(ring) + t * 32;  // this thread's 2 slots

        // prologue: fill stages 0..DEPTH-1, one commit group per stage
        #pragma unroll
        for (int s = 0; s < DEPTH; s++) {
            const float4* src = gin + s * STAGE_F4 + 2 * t;
            cp16(sa + s * 8192, src);
            cp16(sa + s * 8192 + 16, src + 1);
            asm volatile("cp.async.commit_group;" ::: "memory");
        }

        int slot = 0;
        #pragma unroll 1
        for (int s = 0; s < NSTAGES; s++) {
            // oldest group (stage s) complete -> its smem bytes visible
            asm volatile("cp.async.wait_group %0;" :: "n"(DEPTH - 1) : "memory");

            const int li = slot * STAGE_F4 + 2 * t;
            float4 e0 = ring[li];
            float4 e1 = ring[li + 1];

            const int g = base + s * STAGE_F4 + 2 * t;     // even -> one x
            const float xv = __ldg(&x[g >> 8]);

            float4 r0, r1;
            r0.x = fmaf(0.9f, e0.x, xv); r0.y = fmaf(0.9f, e0.y, xv);
            r0.z = fmaf(0.9f, e0.z, xv); r0.w = fmaf(0.9f, e0.w, xv);
            r1.x = fmaf(0.9f, e1.x, xv); r1.y = fmaf(0.9f, e1.y, xv);
            r1.z = fmaf(0.9f, e1.z, xv); r1.w = fmaf(0.9f, e1.w, xv);

            __stcs(gout + s * STAGE_F4 + 2 * t, r0);
            __stcs(gout + s * STAGE_F4 + 2 * t + 1, r1);

            // refill this slot with stage s+DEPTH (its write lands >=600cyc
            // after our LDS above completed -> no smem race)
            if (s < NSTAGES - DEPTH) {
                const float4* src = gin + (s + DEPTH) * STAGE_F4 + 2 * t;
                cp16(sa + slot * 8192, src);
                cp16(sa + slot * 8192 + 16, src + 1);
            }
            // one commit per iteration (empty group past the end) keeps the
            // wait_group counting invariant
            asm volatile("cp.async.commit_group;" ::: "memory");

            slot = (slot == DEPTH - 1) ? 0 : slot + 1;
        }
    } else {
        // ---------------- GEMM + epilogue path ----------------
        // block handles h-tile of 32 columns, all 32 batch rows.
        float* xs = reinterpret_cast<float*>(ring);          // [32][33]
        float* ws = reinterpret_cast<float*>(ring) + 1056;   // [32][32], 16B-aligned

        const int t  = threadIdx.x;
        const int h0 = blockIdx.x * 32;
        const int hx = t & 7;           // which float4 of the 32-h tile
        const int i  = t >> 3;          // batch row 0..31

        float4 acc = make_float4(0.f, 0.f, 0.f, 0.f);

        for (int kt = 0; kt < DD; kt += 32) {
            for (int m = t; m < 1024; m += NTHREADS)
                xs[(m >> 5) * 33 + (m & 31)] = x[(m >> 5) * DD + kt + (m & 31)];
            for (int m = t; m < 1024; m += NTHREADS)
                ws[m] = w[(kt + (m >> 5)) * HH + h0 + (m & 31)];
            __syncthreads();

            #pragma unroll 8
            for (int k = 0; k < 32; k++) {
                float4 wv = reinterpret_cast<const float4*>(&ws[k * 32])[hx];
                float xv = xs[i * 33 + k];
                acc.x = fmaf(xv, wv.x, acc.x);
                acc.y = fmaf(xv, wv.y, acc.y);
                acc.z = fmaf(xv, wv.z, acc.z);
                acc.w = fmaf(xv, wv.w, acc.w);
            }
            __syncthreads();
        }

        // epilogue: z = 0.9*u + x@w + b ; out = tanh(z); u_new = z; E_b
        const int h   = h0 + hx * 4;
        const int idx = i * HH + h;
        float4 bv = *reinterpret_cast<const float4*>(&b[h]);
        float4 uv = *reinterpret_cast<const float4*>(&u[idx]);
        float4 z;
        z.x = fmaf(0.9f, uv.x, acc.x + bv.x);
        z.y = fmaf(0.9f, uv.y, acc.y + bv.y);
        z.z = fmaf(0.9f, uv.z, acc.z + bv.z);
        z.w = fmaf(0.9f, uv.w, acc.w + bv.w);

        *reinterpret_cast<float4*>(&out[OFF_UNEW + idx]) = z;

        float4 o;
        o.x = tanhf(z.x); o.y = tanhf(z.y);
        o.z = tanhf(z.z); o.w = tanhf(z.w);
        *reinterpret_cast<float4*>(&out[idx]) = o;

        float4 ev = *reinterpret_cast<const float4*>(&Eb[idx]);
        float4 e;
        e.x = fmaf(0.9f, ev.x, 1.0f);
        e.y = fmaf(0.9f, ev.y, 1.0f);
        e.z = fmaf(0.9f, ev.z, 1.0f);
        e.w = fmaf(0.9f, ev.w, 1.0f);
        *reinterpret_cast<float4*>(&out[OFF_EB + idx]) = e;
    }
}

extern "C" void kernel_launch(void* const* d_in, const int* in_sizes, int n_in,
                              void* d_out, int out_size) {
    const float* x  = (const float*)d_in[0];  // [32,1024]
    const float* w  = (const float*)d_in[1];  // [1024,1024]
    const float* b  = (const float*)d_in[2];  // [1024]
    const float* u  = (const float*)d_in[3];  // [32,1024]
    const float* Ew = (const float*)d_in[4];  // [1,32,1024,1024]
    const float* Eb = (const float*)d_in[5];  // [1,32,1024]
    float* out = (float*)d_out;

    diag_rtrl_fused_kernel<<<GEMM_BLOCKS + STREAM_BLOCKS, NTHREADS>>>(
        x, w, b, u, Ew, Eb, out);
}

// round 7
// speedup vs baseline: 1.5089x; 1.5089x over previous
#include <cuda_runtime.h>
#include <math.h>

// Problem dims (fixed by the dataset)
#define BB 32
#define DD 1024
#define HH 1024

#define GEMM_BLOCKS 32         // h-tiles of 32: 1024/32
#define STREAM_BLOCKS 8192     // each block: 1024 float4 = 16KB; 8192*1024 = 2^23
#define NTHREADS 256
#define N4 ((BB*DD*HH)/4)      // 8388608 float4

// d_out layout (float32, reference return order):
//   out   [B,H]      @ 0
//   u_new [B,H]      @ 32768
//   E_w   [B,D,H]    @ 65536
//   E_b   [B,H]      @ 65536 + 33554432
#define OFF_UNEW (BB*HH)
#define OFF_EW   (2*BB*HH)
#define OFF_EB   (2*BB*HH + BB*DD*HH)

__global__ void diag_rtrl_fused_kernel(
    const float* __restrict__ x,   // [B,D]
    const float* __restrict__ w,   // [D,H]
    const float* __restrict__ b,   // [H]
    const float* __restrict__ u,   // [B,H]
    const float* __restrict__ Ew,  // [1,B,D,H]
    const float* __restrict__ Eb,  // [1,B,H]
    float* __restrict__ out)       // packed outputs
{
    if (blockIdx.x >= GEMM_BLOCKS) {
        // ---------------- E_w streaming path: one-shot, straight-line ------
        // E_new_w[i,d,h] = 0.9*E_w[i,d,h] + x[i,d]
        // block c covers float4 [c*1024, (c+1)*1024): element range
        // [c*4096,(c+1)*4096) -> x indices 4c..4c+3 (uniform per block!)
        const int c    = blockIdx.x - GEMM_BLOCKS;
        const int base = c << 10;                  // c*1024 float4
        const int t    = threadIdx.x;
        const float4* __restrict__ ein = reinterpret_cast<const float4*>(Ew);
        float4* __restrict__ eo = reinterpret_cast<float4*>(&out[OFF_EW]);

        // uniform x for the whole block: x[4c..4c+3], float4-aligned
        const float4 xv = __ldg(reinterpret_cast<const float4*>(x) + c);

        const int p = base + t;
        // four independent coalesced loads (straight-line -> front-batched)
        float4 e0 = __ldcs(ein + p);
        float4 e1 = __ldcs(ein + p + 256);
        float4 e2 = __ldcs(ein + p + 512);
        float4 e3 = __ldcs(ein + p + 768);

        float4 r0, r1, r2, r3;
        r0.x = fmaf(0.9f, e0.x, xv.x); r0.y = fmaf(0.9f, e0.y, xv.x);
        r0.z = fmaf(0.9f, e0.z, xv.x); r0.w = fmaf(0.9f, e0.w, xv.x);
        r1.x = fmaf(0.9f, e1.x, xv.y); r1.y = fmaf(0.9f, e1.y, xv.y);
        r1.z = fmaf(0.9f, e1.z, xv.y); r1.w = fmaf(0.9f, e1.w, xv.y);
        r2.x = fmaf(0.9f, e2.x, xv.z); r2.y = fmaf(0.9f, e2.y, xv.z);
        r2.z = fmaf(0.9f, e2.z, xv.z); r2.w = fmaf(0.9f, e2.w, xv.z);
        r3.x = fmaf(0.9f, e3.x, xv.w); r3.y = fmaf(0.9f, e3.y, xv.w);
        r3.z = fmaf(0.9f, e3.z, xv.w); r3.w = fmaf(0.9f, e3.w, xv.w);

        __stcs(eo + p, r0);
        __stcs(eo + p + 256, r1);
        __stcs(eo + p + 512, r2);
        __stcs(eo + p + 768, r3);
    } else {
        // ---------------- GEMM + epilogue path ----------------
        // block handles h-tile of 32 columns, all 32 batch rows.
        __shared__ float xs[32][33];                 // [i][k] (+pad)
        __shared__ __align__(16) float ws[32][32];   // [k][h]

        const int t  = threadIdx.x;
        const int h0 = blockIdx.x * 32;
        const int hx = t & 7;           // which float4 of the 32-h tile
        const int i  = t >> 3;          // batch row 0..31

        float4 acc = make_float4(0.f, 0.f, 0.f, 0.f);

        for (int kt = 0; kt < DD; kt += 32) {
            for (int m = t; m < 1024; m += NTHREADS)
                xs[m >> 5][m & 31] = x[(m >> 5) * DD + kt + (m & 31)];
            for (int m = t; m < 1024; m += NTHREADS)
                ws[m >> 5][m & 31] = w[(kt + (m >> 5)) * HH + h0 + (m & 31)];
            __syncthreads();

            #pragma unroll 8
            for (int k = 0; k < 32; k++) {
                float4 wv = reinterpret_cast<const float4*>(&ws[k][0])[hx];
                float xv = xs[i][k];
                acc.x = fmaf(xv, wv.x, acc.x);
                acc.y = fmaf(xv, wv.y, acc.y);
                acc.z = fmaf(xv, wv.z, acc.z);
                acc.w = fmaf(xv, wv.w, acc.w);
            }
            __syncthreads();
        }

        // epilogue: z = 0.9*u + x@w + b ; out = tanh(z); u_new = z; E_b
        const int h   = h0 + hx * 4;
        const int idx = i * HH + h;
        float4 bv = *reinterpret_cast<const float4*>(&b[h]);
        float4 uv = *reinterpret_cast<const float4*>(&u[idx]);
        float4 z;
        z.x = fmaf(0.9f, uv.x, acc.x + bv.x);
        z.y = fmaf(0.9f, uv.y, acc.y + bv.y);
        z.z = fmaf(0.9f, uv.z, acc.z + bv.z);
        z.w = fmaf(0.9f, uv.w, acc.w + bv.w);

        *reinterpret_cast<float4*>(&out[OFF_UNEW + idx]) = z;

        float4 o;
        o.x = tanhf(z.x); o.y = tanhf(z.y);
        o.z = tanhf(z.z); o.w = tanhf(z.w);
        *reinterpret_cast<float4*>(&out[idx]) = o;

        float4 ev = *reinterpret_cast<const float4*>(&Eb[idx]);
        float4 e;
        e.x = fmaf(0.9f, ev.x, 1.0f);
        e.y = fmaf(0.9f, ev.y, 1.0f);
        e.z = fmaf(0.9f, ev.z, 1.0f);
        e.w = fmaf(0.9f, ev.w, 1.0f);
        *reinterpret_cast<float4*>(&out[OFF_EB + idx]) = e;
    }
}

extern "C" void kernel_launch(void* const* d_in, const int* in_sizes, int n_in,
                              void* d_out, int out_size) {
    const float* x  = (const float*)d_in[0];  // [32,1024]
    const float* w  = (const float*)d_in[1];  // [1024,1024]
    const float* b  = (const float*)d_in[2];  // [1024]
    const float* u  = (const float*)d_in[3];  // [32,1024]
    const float* Ew = (const float*)d_in[4];  // [1,32,1024,1024]
    const float* Eb = (const float*)d_in[5];  // [1,32,1024]
    float* out = (float*)d_out;

    diag_rtrl_fused_kernel<<<GEMM_BLOCKS + STREAM_BLOCKS, NTHREADS>>>(
        x, w, b, u, Ew, Eb, out);
}

// round 8
// speedup vs baseline: 1.5564x; 1.0315x over previous
#include <cuda_runtime.h>
#include <math.h>

// Problem dims (fixed by the dataset)
#define BB 32
#define DD 1024
#define HH 1024

#define GEMM_BLOCKS 32        // h-tiles of 32: 1024/32
#define STREAM_BLOCKS 1024    // stride 262144 f4; 2^23 / 262144 = 32 -> 8 outer iters
#define NTHREADS 256
#define N4 ((BB*DD*HH)/4)     // 8388608 float4

// d_out layout (float32, reference return order):
//   out   [B,H]      @ 0
//   u_new [B,H]      @ 32768
//   E_w   [B,D,H]    @ 65536
//   E_b   [B,H]      @ 65536 + 33554432
#define OFF_UNEW (BB*HH)
#define OFF_EW   (2*BB*HH)
#define OFF_EB   (2*BB*HH + BB*DD*HH)

// Forced-MLP load/store: volatile asm can't be reordered or interleaved,
// so ptxas MUST emit 4 back-to-back LDG.E.128 with all 16 results live.
#define LDG4CS(v, ptr)                                                     \
    asm volatile("ld.global.cs.v4.f32 {%0,%1,%2,%3}, [%4];"                \
                 : "=f"((v).x), "=f"((v).y), "=f"((v).z), "=f"((v).w)      \
                 : "l"(ptr))
#define STG4CS(ptr, v)                                                     \
    asm volatile("st.global.cs.v4.f32 [%0], {%1,%2,%3,%4};"                \
                 :: "l"(ptr), "f"((v).x), "f"((v).y), "f"((v).z), "f"((v).w) \
                 : "memory")

__global__ void diag_rtrl_fused_kernel(
    const float* __restrict__ x,   // [B,D]
    const float* __restrict__ w,   // [D,H]
    const float* __restrict__ b,   // [H]
    const float* __restrict__ u,   // [B,H]
    const float* __restrict__ Ew,  // [1,B,D,H]
    const float* __restrict__ Eb,  // [1,B,H]
    float* __restrict__ out)       // packed outputs
{
    if (blockIdx.x >= GEMM_BLOCKS) {
        // ---------------- E_w streaming path ----------------
        // E_new_w[i,d,h] = 0.9*E_w[i,d,h] + x[i,d]; f4 index p -> x[p>>8]
        const float4* __restrict__ ein = reinterpret_cast<const float4*>(Ew);
        float4* __restrict__ eo = reinterpret_cast<float4*>(&out[OFF_EW]);

        constexpr int stride = STREAM_BLOCKS * NTHREADS;  // 262144
        int p = (blockIdx.x - GEMM_BLOCKS) * NTHREADS + threadIdx.x;

        #pragma unroll 1
        for (int it = 0; it < 8; it++) {
            const float4* a0 = ein + p;
            const float4* a1 = ein + p + stride;
            const float4* a2 = ein + p + 2 * stride;
            const float4* a3 = ein + p + 3 * stride;

            float4 e0, e1, e2, e3;
            LDG4CS(e0, a0);            // 4 consecutive LDG.E.128 guaranteed
            LDG4CS(e1, a1);
            LDG4CS(e2, a2);
            LDG4CS(e3, a3);

            const float x0 = __ldg(&x[p >> 8]);
            const float x1 = __ldg(&x[(p + stride) >> 8]);
            const float x2 = __ldg(&x[(p + 2 * stride) >> 8]);
            const float x3 = __ldg(&x[(p + 3 * stride) >> 8]);

            // write results back into the load regs (cap register pressure)
            e0.x = fmaf(0.9f, e0.x, x0); e0.y = fmaf(0.9f, e0.y, x0);
            e0.z = fmaf(0.9f, e0.z, x0); e0.w = fmaf(0.9f, e0.w, x0);
            e1.x = fmaf(0.9f, e1.x, x1); e1.y = fmaf(0.9f, e1.y, x1);
            e1.z = fmaf(0.9f, e1.z, x1); e1.w = fmaf(0.9f, e1.w, x1);
            e2.x = fmaf(0.9f, e2.x, x2); e2.y = fmaf(0.9f, e2.y, x2);
            e2.z = fmaf(0.9f, e2.z, x2); e2.w = fmaf(0.9f, e2.w, x2);
            e3.x = fmaf(0.9f, e3.x, x3); e3.y = fmaf(0.9f, e3.y, x3);
            e3.z = fmaf(0.9f, e3.z, x3); e3.w = fmaf(0.9f, e3.w, x3);

            STG4CS(eo + p, e0);
            STG4CS(eo + p + stride, e1);
            STG4CS(eo + p + 2 * stride, e2);
            STG4CS(eo + p + 3 * stride, e3);

            p += 4 * stride;
        }
    } else {
        // ---------------- GEMM + epilogue path ----------------
        // block handles h-tile of 32 columns, all 32 batch rows.
        __shared__ float xs[32][33];                 // [i][k] (+pad)
        __shared__ __align__(16) float ws[32][32];   // [k][h]

        const int t  = threadIdx.x;
        const int h0 = blockIdx.x * 32;
        const int hx = t & 7;           // which float4 of the 32-h tile
        const int i  = t >> 3;          // batch row 0..31

        float4 acc = make_float4(0.f, 0.f, 0.f, 0.f);

        for (int kt = 0; kt < DD; kt += 32) {
            for (int m = t; m < 1024; m += NTHREADS)
                xs[m >> 5][m & 31] = x[(m >> 5) * DD + kt + (m & 31)];
            for (int m = t; m < 1024; m += NTHREADS)
                ws[m >> 5][m & 31] = w[(kt + (m >> 5)) * HH + h0 + (m & 31)];
            __syncthreads();

            #pragma unroll 8
            for (int k = 0; k < 32; k++) {
                float4 wv = reinterpret_cast<const float4*>(&ws[k][0])[hx];
                float xv = xs[i][k];
                acc.x = fmaf(xv, wv.x, acc.x);
                acc.y = fmaf(xv, wv.y, acc.y);
                acc.z = fmaf(xv, wv.z, acc.z);
                acc.w = fmaf(xv, wv.w, acc.w);
            }
            __syncthreads();
        }

        // epilogue: z = 0.9*u + x@w + b ; out = tanh(z); u_new = z; E_b
        const int h   = h0 + hx * 4;
        const int idx = i * HH + h;
        float4 bv = *reinterpret_cast<const float4*>(&b[h]);
        float4 uv = *reinterpret_cast<const float4*>(&u[idx]);
        float4 z;
        z.x = fmaf(0.9f, uv.x, acc.x + bv.x);
        z.y = fmaf(0.9f, uv.y, acc.y + bv.y);
        z.z = fmaf(0.9f, uv.z, acc.z + bv.z);
        z.w = fmaf(0.9f, uv.w, acc.w + bv.w);

        *reinterpret_cast<float4*>(&out[OFF_UNEW + idx]) = z;

        float4 o;
        o.x = tanhf(z.x); o.y = tanhf(z.y);
        o.z = tanhf(z.z); o.w = tanhf(z.w);
        *reinterpret_cast<float4*>(&out[idx]) = o;

        float4 ev = *reinterpret_cast<const float4*>(&Eb[idx]);
        float4 e;
        e.x = fmaf(0.9f, ev.x, 1.0f);
        e.y = fmaf(0.9f, ev.y, 1.0f);
        e.z = fmaf(0.9f, ev.z, 1.0f);
        e.w = fmaf(0.9f, ev.w, 1.0f);
        *reinterpret_cast<float4*>(&out[OFF_EB + idx]) = e;
    }
}

extern "C" void kernel_launch(void* const* d_in, const int* in_sizes, int n_in,
                              void* d_out, int out_size) {
    const float* x  = (const float*)d_in[0];  // [32,1024]
    const float* w  = (const float*)d_in[1];  // [1024,1024]
    const float* b  = (const float*)d_in[2];  // [1024]
    const float* u  = (const float*)d_in[3];  // [32,1024]
    const float* Ew = (const float*)d_in[4];  // [1,32,1024,1024]
    const float* Eb = (const float*)d_in[5];  // [1,32,1024]
    float* out = (float*)d_out;

    diag_rtrl_fused_kernel<<<GEMM_BLOCKS + STREAM_BLOCKS, NTHREADS>>>(
        x, w, b, u, Ew, Eb, out);
}